// round 8
// baseline (speedup 1.0000x reference)
#include <cuda_runtime.h>
#include <math.h>

// out[b,i,j] = pos_biases[j - i + n - 1]
//            + ts_w[ clamp( floor( log(clip(|f32(t[min(i+1,n-1)]) - f32(t[j])|, 1, 1e9)) / 0.301 ), 0, nb ) ]
//
// Exact thresholds (host-built, by-value param): thr[k] = smallest f32 x with
// floor(fdiv_rn(log_rn(x), 0.301f)) >= k.  s_tab[k] = (thr[k], w[k-1], w[k], thr[k+1]).
//
// Run-coherence fast path: timestamps sorted -> |dt| piecewise monotone along j.
// Per 4-element group: if endpoint diffs share sign AND both endpoints land in
// the same exact bucket run, ONE log + ONE table read serves all 4 elements.
// Otherwise exact per-element fallback (identical numerics to R3-R6).

struct ThrTab { float thr[81]; };

__global__ void __launch_bounds__(256)
bias_kernel(const int*   __restrict__ ts,
            const float* __restrict__ pos,
            const float* __restrict__ tsw,
            float*       __restrict__ out,
            int n, int nb, ThrTab tab) {
    extern __shared__ float sm[];
    float4* s_tab = (float4*)sm;              // 80 x (thr[k], w[k-1], w[k], thr[k+1])
    float*  s_pos = sm + 320;                 // n + 16 floats

    const int b   = blockIdx.y;
    const int i0  = blockIdx.x * 8;
    const int tid = threadIdx.x;
    const int* trow = ts + (size_t)b * n;

    if (tid < 80) {
        int k = tid;
        float wkm1 = tsw[min(max(k - 1, 0), nb)];
        float wk   = tsw[min(k, nb)];
        s_tab[k] = make_float4(tab.thr[k], wkm1, wk, tab.thr[k + 1]);
    }
    const int pbase = n - 8 - i0;
    for (int idx = tid; idx < n + 16; idx += 256) {
        int g = pbase + idx;
        s_pos[idx] = (g >= 0 && g <= 2 * n - 2) ? pos[g] : 0.0f;
    }
    __syncthreads();

    float tnr[8];
    #pragma unroll
    for (int r = 0; r < 8; ++r) tnr[r] = (float)__ldg(&trow[min(i0 + r + 1, n - 1)]);

    const int rlim = min(8, n - i0);
    float* oblk = out + ((size_t)b * n + i0) * (size_t)n;

    for (int jj = tid * 4; jj < n; jj += 1024) {
        int4 ti = *reinterpret_cast<const int4*>(trow + jj);
        const float tv0 = (float)ti.x, tv1 = (float)ti.y,
                    tv2 = (float)ti.z, tv3 = (float)ti.w;
        float4 p0 = *reinterpret_cast<const float4*>(s_pos + jj);
        float4 p1 = *reinterpret_cast<const float4*>(s_pos + jj + 4);
        float4 p2 = *reinterpret_cast<const float4*>(s_pos + jj + 8);
        const float pw[12] = {p0.x, p0.y, p0.z, p0.w,
                              p1.x, p1.y, p1.z, p1.w,
                              p2.x, p2.y, p2.z, p2.w};
        float* op = oblk + jj;

        #pragma unroll
        for (int r = 0; r < 8; ++r) {
            const float tn = tnr[r];
            const float d0 = tn - tv0;
            const float d3 = tn - tv3;
            const float a0 = fmaxf(fabsf(d0), 1.0f);
            const float a3 = fmaxf(fabsf(d3), 1.0f);
            const float xlo = fminf(a0, a3);
            const float xhi = fmaxf(a0, a3);

            float q = fmaf(__log2f(xlo), 2.3028145f, 1.25e-4f);
            float4 te = s_tab[(int)q];
            const bool inlo = (xlo >= te.x);          // exact bucket of xlo
            const float wc  = inlo ? te.z : te.y;
            const float hb  = inlo ? te.w : te.x;     // exclusive run upper bound
            const bool same = ((__float_as_int(d0) ^ __float_as_int(d3)) >= 0);
            const bool coh  = same && (xhi < hb);

            float w0, w1, w2, w3;
            if (coh) {
                w0 = w1 = w2 = w3 = wc;               // whole group in one run
            } else {                                  // exact per-element (rare)
                {
                    float x = fmaxf(fabsf(tn - tv0), 1.0f);
                    float qq = fmaf(__log2f(x), 2.3028145f, 1.25e-4f);
                    float4 t4e = s_tab[(int)qq];
                    w0 = (x < t4e.x) ? t4e.y : t4e.z;
                }
                {
                    float x = fmaxf(fabsf(tn - tv1), 1.0f);
                    float qq = fmaf(__log2f(x), 2.3028145f, 1.25e-4f);
                    float4 t4e = s_tab[(int)qq];
                    w1 = (x < t4e.x) ? t4e.y : t4e.z;
                }
                {
                    float x = fmaxf(fabsf(tn - tv2), 1.0f);
                    float qq = fmaf(__log2f(x), 2.3028145f, 1.25e-4f);
                    float4 t4e = s_tab[(int)qq];
                    w2 = (x < t4e.x) ? t4e.y : t4e.z;
                }
                {
                    float x = fmaxf(fabsf(tn - tv3), 1.0f);
                    float qq = fmaf(__log2f(x), 2.3028145f, 1.25e-4f);
                    float4 t4e = s_tab[(int)qq];
                    w3 = (x < t4e.x) ? t4e.y : t4e.z;
                }
            }

            if (r < rlim) {
                float4 o;
                o.x = w0 + pw[7 - r];
                o.y = w1 + pw[8 - r];
                o.z = w2 + pw[9 - r];
                o.w = w3 + pw[10 - r];
                *reinterpret_cast<float4*>(op) = o;
            }
            op += n;
        }
    }
}

static void build_thresholds_host(ThrTab* tab) {
    typedef union { float f; unsigned u; } FU;
    for (int k = 0; k < 81; ++k) {
        if (k == 0) { tab->thr[0] = 1.0f; continue; }
        volatile float kb = 0.301f;                  // force f32 division semantics
        FU l; l.f = (float)(0.301 * (double)k);
        while (!((float)(l.f / kb) >= (float)k)) l.u += 1u;
        for (;;) {
            FU p; p.u = l.u - 1u;
            if ((float)(p.f / kb) >= (float)k) l.u = p.u; else break;
        }
        FU x; x.f = (float)exp((double)l.f);
        while (!((float)log((double)x.f) >= l.f)) x.u += 1u;
        for (;;) {
            FU p; p.u = x.u - 1u;
            if ((float)log((double)p.f) >= l.f) x.u = p.u; else break;
        }
        tab->thr[k] = x.f;
    }
}

extern "C" void kernel_launch(void* const* d_in, const int* in_sizes, int n_in,
                              void* d_out, int out_size) {
    const int*   ts  = (const int*)d_in[0];     // timestamps (B*N) int32
    const float* pos = (const float*)d_in[1];   // pos_biases (2N-1) f32
    const float* tsw = (const float*)d_in[2];   // ts_w (nb+1) f32

    const int n  = (in_sizes[1] + 1) / 2;
    const int B  = in_sizes[0] / n;
    const int nb = in_sizes[2] - 1;

    ThrTab tab;
    build_thresholds_host(&tab);

    size_t smem = (size_t)(320 + n + 16) * sizeof(float);
    dim3 grid((n + 7) / 8, B);
    bias_kernel<<<grid, 256, smem>>>(ts, pos, tsw, (float*)d_out, n, nb, tab);
}